// round 5
// baseline (speedup 1.0000x reference)
#include <cuda_runtime.h>
#include <cuda_bf16.h>
#include <cstdint>

// Problem constants
#define BATCH 2
#define SEQ   2048
#define EMB   2048
#define HEADS 16
#define HDIM  128
#define ROWS  (BATCH * SEQ)          // 4096
#define QKV_N (3 * EMB)              // 6144
#define NEG_INF (-__int_as_float(0x7f800000))

// ---------------------------------------------------------------------------
// Scratch (device globals — no allocation allowed)
// ---------------------------------------------------------------------------
__device__ float g_qkv[(size_t)ROWS * QKV_N];   // [4096, 6144] row-major
__device__ float g_ctx[(size_t)ROWS * EMB];     // [4096, 2048] row-major

// ---------------------------------------------------------------------------
// fp32 tiled GEMM: C[M,N] = A[M,K] @ B[K,N], all row-major, dims % tile == 0
// 128x128 tile, BK=8, 256 threads, 8x8 microtile per thread
// ---------------------------------------------------------------------------
#define GBM 128
#define GBN 128
#define GBK 8
#define APAD 132

__global__ __launch_bounds__(256) void gemm_f32_kernel(
    const float* __restrict__ A, const float* __restrict__ Bm,
    float* __restrict__ C, int M, int N, int K)
{
    __shared__ float As[GBK][APAD];   // transposed A tile [k][m], padded
    __shared__ float Bs[GBK][GBN];

    const int tid = threadIdx.x;
    const int bm = blockIdx.y * GBM;
    const int bn = blockIdx.x * GBN;
    const int tx = tid & 15;
    const int ty = tid >> 4;

    // load mapping
    const int arow = tid >> 1;            // 0..127
    const int acol = (tid & 1) << 2;      // 0 or 4
    const int brow = tid >> 5;            // 0..7
    const int bcol = (tid & 31) << 2;     // 0..124

    float acc[8][8];
#pragma unroll
    for (int i = 0; i < 8; i++)
#pragma unroll
        for (int j = 0; j < 8; j++) acc[i][j] = 0.f;

    const float* Aptr = A + (size_t)(bm + arow) * K + acol;
    const float* Bptr = Bm + (size_t)brow * N + bn + bcol;

    for (int k0 = 0; k0 < K; k0 += GBK) {
        float4 av = *(const float4*)(Aptr + k0);
        float4 bv = *(const float4*)(Bptr + (size_t)k0 * N);
        As[acol + 0][arow] = av.x;
        As[acol + 1][arow] = av.y;
        As[acol + 2][arow] = av.z;
        As[acol + 3][arow] = av.w;
        *(float4*)&Bs[brow][bcol] = bv;
        __syncthreads();

#pragma unroll
        for (int kk = 0; kk < GBK; kk++) {
            float a[8], b[8];
            *(float4*)(a)     = *(const float4*)&As[kk][ty * 4];
            *(float4*)(a + 4) = *(const float4*)&As[kk][ty * 4 + 64];
            *(float4*)(b)     = *(const float4*)&Bs[kk][tx * 4];
            *(float4*)(b + 4) = *(const float4*)&Bs[kk][tx * 4 + 64];
#pragma unroll
            for (int i = 0; i < 8; i++)
#pragma unroll
                for (int j = 0; j < 8; j++)
                    acc[i][j] += a[i] * b[j];
        }
        __syncthreads();
    }

#pragma unroll
    for (int i = 0; i < 8; i++) {
        int rl = (i < 4) ? (ty * 4 + i) : (64 + ty * 4 + (i - 4));
        float* Crow = C + (size_t)(bm + rl) * N + bn;
        float4 v0 = make_float4(acc[i][0], acc[i][1], acc[i][2], acc[i][3]);
        float4 v1 = make_float4(acc[i][4], acc[i][5], acc[i][6], acc[i][7]);
        *(float4*)(Crow + tx * 4)      = v0;
        *(float4*)(Crow + tx * 4 + 64) = v1;
    }
}

// ---------------------------------------------------------------------------
// fp32 causal flash attention
// grid: (S/64 q-tiles, B*H). block 256 threads (16x16 over 64x64 S tile).
// Each thread: rows {ty+16i}, S-cols {tx+16j}, O-cols {tx+16j, j<8}.
// Smem: Qs[64][129], KVs[64][129] (K then V reuse), Ps[64][65] = 82688 B.
// ---------------------------------------------------------------------------
#define AM 64
#define AN 64
#define QPAD 129
#define PPAD 65
#define ATTN_SMEM ((2 * AM * QPAD + AM * PPAD) * 4)

__global__ __launch_bounds__(256) void attn_kernel(
    const float* __restrict__ qkv, float* __restrict__ ctx)
{
    extern __shared__ float sm[];
    float* Qs  = sm;                     // 64*129
    float* KVs = Qs + AM * QPAD;         // 64*129
    float* Ps  = KVs + AM * QPAD;        // 64*65

    const int tid = threadIdx.x;
    const int tx = tid & 15;
    const int ty = tid >> 4;
    const int qt = (gridDim.x - 1) - blockIdx.x;  // longest blocks first
    const int bh = blockIdx.y;
    const int b = bh >> 4;
    const int h = bh & 15;
    const int q0 = qt * AM;

    const size_t ld = QKV_N;  // 6144
    const float* qbase = qkv + (size_t)b * SEQ * ld + (size_t)h * HDIM;
    const float* kbase = qbase + EMB;
    const float* vbase = qbase + 2 * EMB;

    // Load Q tile [64,128]
    for (int it = tid; it < AM * 32; it += 256) {
        int r = it >> 5;
        int c4 = (it & 31) << 2;
        float4 v = *(const float4*)(qbase + (size_t)(q0 + r) * ld + c4);
        float* d = &Qs[r * QPAD + c4];
        d[0] = v.x; d[1] = v.y; d[2] = v.z; d[3] = v.w;
    }

    float m_i[4], l_i[4], o[4][8];
#pragma unroll
    for (int i = 0; i < 4; i++) {
        m_i[i] = NEG_INF;
        l_i[i] = 0.f;
#pragma unroll
        for (int j = 0; j < 8; j++) o[i][j] = 0.f;
    }

    const float scale = 0.08838834764831845f;  // 1/sqrt(128)

    for (int kt = 0; kt <= qt; ++kt) {
        const int k0 = kt * AN;
        __syncthreads();  // prev iter done with KVs / Ps

        // Load K tile into KVs
        for (int it = tid; it < AN * 32; it += 256) {
            int r = it >> 5;
            int c4 = (it & 31) << 2;
            float4 v = *(const float4*)(kbase + (size_t)(k0 + r) * ld + c4);
            float* d = &KVs[r * QPAD + c4];
            d[0] = v.x; d[1] = v.y; d[2] = v.z; d[3] = v.w;
        }
        __syncthreads();

        // S = Q @ K^T (64x64), 4x4 per thread
        float s[4][4];
#pragma unroll
        for (int i = 0; i < 4; i++)
#pragma unroll
            for (int j = 0; j < 4; j++) s[i][j] = 0.f;

#pragma unroll 4
        for (int d = 0; d < HDIM; ++d) {
            float a_[4], b_[4];
#pragma unroll
            for (int i = 0; i < 4; i++) a_[i] = Qs[(ty + 16 * i) * QPAD + d];
#pragma unroll
            for (int j = 0; j < 4; j++) b_[j] = KVs[(tx + 16 * j) * QPAD + d];
#pragma unroll
            for (int i = 0; i < 4; i++)
#pragma unroll
                for (int j = 0; j < 4; j++)
                    s[i][j] += a_[i] * b_[j];
        }

        const bool diag = (kt == qt);
        // scale + causal mask + row max
        float mt[4];
#pragma unroll
        for (int i = 0; i < 4; i++) {
            int qg = q0 + ty + 16 * i;
            float mx = NEG_INF;
#pragma unroll
            for (int j = 0; j < 4; j++) {
                float v = s[i][j] * scale;
                if (diag && (k0 + tx + 16 * j) > qg) v = NEG_INF;
                s[i][j] = v;
                mx = fmaxf(mx, v);
            }
#pragma unroll
            for (int off = 8; off > 0; off >>= 1)
                mx = fmaxf(mx, __shfl_xor_sync(0xffffffffu, mx, off));
            mt[i] = mx;
        }

        // online softmax update; write P to smem
#pragma unroll
        for (int i = 0; i < 4; i++) {
            float mnew = fmaxf(m_i[i], mt[i]);
            float alpha = __expf(m_i[i] - mnew);
            float lsum = 0.f;
#pragma unroll
            for (int j = 0; j < 4; j++) {
                float p = __expf(s[i][j] - mnew);  // exp(-inf) = 0
                s[i][j] = p;
                lsum += p;
            }
#pragma unroll
            for (int off = 8; off > 0; off >>= 1)
                lsum += __shfl_xor_sync(0xffffffffu, lsum, off);
            l_i[i] = l_i[i] * alpha + lsum;
            m_i[i] = mnew;
#pragma unroll
            for (int j = 0; j < 8; j++) o[i][j] *= alpha;
#pragma unroll
            for (int j = 0; j < 4; j++)
                Ps[(ty + 16 * i) * PPAD + tx + 16 * j] = s[i][j];
        }
        __syncthreads();  // Ps visible; all S-reads of KVs (K) done

        // Load V tile into KVs (reuse buffer)
        for (int it = tid; it < AN * 32; it += 256) {
            int r = it >> 5;
            int c4 = (it & 31) << 2;
            float4 v = *(const float4*)(vbase + (size_t)(k0 + r) * ld + c4);
            float* d = &KVs[r * QPAD + c4];
            d[0] = v.x; d[1] = v.y; d[2] = v.z; d[3] = v.w;
        }
        __syncthreads();

        // O += P @ V  (64x128), 4x8 per thread
#pragma unroll 8
        for (int k = 0; k < AN; ++k) {
            float pv[4], vv[8];
#pragma unroll
            for (int i = 0; i < 4; i++) pv[i] = Ps[(ty + 16 * i) * PPAD + k];
#pragma unroll
            for (int j = 0; j < 8; j++) vv[j] = KVs[k * QPAD + tx + 16 * j];
#pragma unroll
            for (int i = 0; i < 4; i++)
#pragma unroll
                for (int j = 0; j < 8; j++)
                    o[i][j] += pv[i] * vv[j];
        }
    }

    // Epilogue: normalize and write ctx [b, s, h*128 + d]
#pragma unroll
    for (int i = 0; i < 4; i++) {
        float inv = 1.f / l_i[i];
        int r = q0 + ty + 16 * i;
        float* crow = ctx + (size_t)(b * SEQ + r) * EMB + h * HDIM;
#pragma unroll
        for (int j = 0; j < 8; j++)
            crow[tx + 16 * j] = o[i][j] * inv;
    }
}

// ---------------------------------------------------------------------------
// Launch
// ---------------------------------------------------------------------------
extern "C" void kernel_launch(void* const* d_in, const int* in_sizes, int n_in,
                              void* d_out, int out_size)
{
    const float* x     = (const float*)d_in[0];
    const float* w_qkv = (const float*)d_in[1];
    const float* w_out = (const float*)d_in[2];
    float* out = (float*)d_out;

    float* qkv = nullptr;
    float* ctx = nullptr;
    cudaGetSymbolAddress((void**)&qkv, g_qkv);
    cudaGetSymbolAddress((void**)&ctx, g_ctx);

    cudaFuncSetAttribute(attn_kernel,
                         cudaFuncAttributeMaxDynamicSharedMemorySize, ATTN_SMEM);

    // 1) QKV projection: [4096,2048] @ [2048,6144] -> [4096,6144]
    {
        dim3 grid(QKV_N / GBN, ROWS / GBM);  // (48, 32)
        gemm_f32_kernel<<<grid, 256>>>(x, w_qkv, qkv, ROWS, QKV_N, EMB);
    }

    // 2) Causal flash attention -> ctx [4096, 2048]
    {
        dim3 grid(SEQ / AM, BATCH * HEADS);  // (32, 32)
        attn_kernel<<<grid, 256, ATTN_SMEM>>>(qkv, ctx);
    }

    // 3) Output projection: [4096,2048] @ [2048,2048] -> out
    {
        dim3 grid(EMB / GBN, ROWS / GBM);    // (16, 32)
        gemm_f32_kernel<<<grid, 256>>>(ctx, w_out, out, ROWS, EMB, EMB);
    }
}

// round 10
// speedup vs baseline: 1.7263x; 1.7263x over previous
#include <cuda_runtime.h>
#include <cuda_bf16.h>
#include <cstdint>

// Problem constants
#define BATCH 2
#define SEQ   2048
#define EMB   2048
#define HEADS 16
#define HDIM  128
#define ROWS  (BATCH * SEQ)          // 4096
#define QKV_N (3 * EMB)              // 6144
#define NEG_INF (-__int_as_float(0x7f800000))

// ---------------------------------------------------------------------------
// Scratch (device globals — no allocation allowed)
// ---------------------------------------------------------------------------
__device__ float g_qkv[(size_t)ROWS * QKV_N];            // [4096, 6144]
__device__ float g_ctx[(size_t)ROWS * EMB];              // [4096, 2048]
__device__ __nv_bfloat16 g_ah[(size_t)ROWS * EMB];       // A hi (x, then ctx)
__device__ __nv_bfloat16 g_al[(size_t)ROWS * EMB];       // A lo
__device__ __nv_bfloat16 g_wqkv_h[(size_t)QKV_N * EMB];  // w_qkv^T hi [6144,2048]
__device__ __nv_bfloat16 g_wqkv_l[(size_t)QKV_N * EMB];
__device__ __nv_bfloat16 g_wout_h[(size_t)EMB * EMB];    // w_out^T hi [2048,2048]
__device__ __nv_bfloat16 g_wout_l[(size_t)EMB * EMB];

// ---------------------------------------------------------------------------
// Family-wide (sm_103-legal) helpers: ldmatrix + mma.sync + cp.async
// ---------------------------------------------------------------------------
__device__ __forceinline__ uint32_t smem_u32(const void* p) {
    uint32_t a;
    asm("{ .reg .u64 t; cvta.to.shared.u64 t, %1; cvt.u32.u64 %0, t; }"
        : "=r"(a) : "l"(p));
    return a;
}

#define CP_ASYNC16(dst, src) \
    asm volatile("cp.async.cg.shared.global [%0], [%1], 16;" \
        :: "r"(dst), "l"(src))
#define CP_COMMIT() asm volatile("cp.async.commit_group;" ::: "memory")
#define CP_WAIT(N)  asm volatile("cp.async.wait_group %0;" :: "n"(N) : "memory")

__device__ __forceinline__ void ldsm_x4(uint32_t* r, uint32_t addr) {
    asm volatile("ldmatrix.sync.aligned.m8n8.x4.shared.b16 {%0,%1,%2,%3}, [%4];"
        : "=r"(r[0]), "=r"(r[1]), "=r"(r[2]), "=r"(r[3]) : "r"(addr));
}

__device__ __forceinline__ void mma_bf16(float* d, const uint32_t* a,
                                         const uint32_t* b) {
    asm volatile(
        "mma.sync.aligned.m16n8k16.row.col.f32.bf16.bf16.f32 "
        "{%0,%1,%2,%3}, {%4,%5,%6,%7}, {%8,%9}, {%0,%1,%2,%3};"
        : "+f"(d[0]), "+f"(d[1]), "+f"(d[2]), "+f"(d[3])
        : "r"(a[0]), "r"(a[1]), "r"(a[2]), "r"(a[3]), "r"(b[0]), "r"(b[1]));
}

// ---------------------------------------------------------------------------
// fp32 -> (hi, lo) bf16 split, elementwise (vectorized x4)
// ---------------------------------------------------------------------------
__global__ __launch_bounds__(256) void split_kernel(
    const float* __restrict__ X, __nv_bfloat16* __restrict__ Hi,
    __nv_bfloat16* __restrict__ Lo, int n4)
{
    int i = blockIdx.x * 256 + threadIdx.x;
    if (i >= n4) return;
    float4 v = ((const float4*)X)[i];
    float vv[4] = {v.x, v.y, v.z, v.w};
    __nv_bfloat16 h[4], l[4];
#pragma unroll
    for (int j = 0; j < 4; j++) {
        h[j] = __float2bfloat16(vv[j]);
        l[j] = __float2bfloat16(vv[j] - __bfloat162float(h[j]));
    }
    __nv_bfloat162* Hp = (__nv_bfloat162*)(Hi + 4 * (size_t)i);
    __nv_bfloat162* Lp = (__nv_bfloat162*)(Lo + 4 * (size_t)i);
    Hp[0] = __halves2bfloat162(h[0], h[1]);
    Hp[1] = __halves2bfloat162(h[2], h[3]);
    Lp[0] = __halves2bfloat162(l[0], l[1]);
    Lp[1] = __halves2bfloat162(l[2], l[3]);
}

// ---------------------------------------------------------------------------
// fp32 W[K][N] -> bf16 hi/lo W^T[N][K] (tiled transpose)
// ---------------------------------------------------------------------------
__global__ __launch_bounds__(256) void split_transpose_kernel(
    const float* __restrict__ W, __nv_bfloat16* __restrict__ Th,
    __nv_bfloat16* __restrict__ Tl, int K, int N)
{
    __shared__ float t[32][33];
    const int n0 = blockIdx.x * 32;
    const int k0 = blockIdx.y * 32;
    const int tx = threadIdx.x & 31;
    const int ty = threadIdx.x >> 5;   // 0..7
#pragma unroll
    for (int i = 0; i < 4; ++i)
        t[ty + 8 * i][tx] = W[(size_t)(k0 + ty + 8 * i) * N + n0 + tx];
    __syncthreads();
#pragma unroll
    for (int i = 0; i < 4; ++i) {
        float v = t[tx][ty + 8 * i];
        __nv_bfloat16 h = __float2bfloat16(v);
        __nv_bfloat16 l = __float2bfloat16(v - __bfloat162float(h));
        size_t o = (size_t)(n0 + ty + 8 * i) * K + k0 + tx;
        Th[o] = h;
        Tl[o] = l;
    }
}

// ---------------------------------------------------------------------------
// bf16 hi/lo 3-term GEMM via mma.sync (HMMA):
//   C[M,N] = (Ah+Al)[M,K] @ (Bh+Bl)^T, B stored [N,K] K-major
// CTA 128x128, BK=32 bf16, 8 warps (warp tile 32m x 64n), 4-stage cp.async.
// Smem tile row = 32 bf16 = 64B, XOR-swizzled for conflict-free ldmatrix.
// ---------------------------------------------------------------------------
#define GM 128
#define GN 128
#define GKC 32
#define TILE_B 8192                 // 128 rows * 64 B
#define STAGE_B (4 * TILE_B)        // Ah, Al, Bh, Bl tiles
#define NSTAGE 4
#define GEMM_SMEM (NSTAGE * STAGE_B)  // 131072

__device__ __forceinline__ uint32_t swz(int row, int ch) {
    // row*64 bytes + 16B chunk, chunk XOR'd by (row>>1)&3
    return (uint32_t)(row * 64 + ((ch ^ ((row >> 1) & 3)) << 4));
}

__global__ __launch_bounds__(256, 1) void gemm_tc_kernel(
    const __nv_bfloat16* __restrict__ Ah, const __nv_bfloat16* __restrict__ Al,
    const __nv_bfloat16* __restrict__ Bh, const __nv_bfloat16* __restrict__ Bl,
    float* __restrict__ C, int M, int N, int K)
{
    extern __shared__ char smc[];
    const uint32_t sbase = smem_u32(smc);
    const int tid = threadIdx.x;
    const int lane = tid & 31;
    const int wid = tid >> 5;
    const int wm = wid & 3;          // 4 m-tiles of 32 rows
    const int wn = wid >> 2;         // 2 n-tiles of 64 cols
    const int bn = blockIdx.x * GN;
    const int bm = blockIdx.y * GM;
    const int nchunk = K / GKC;

    const __nv_bfloat16* gsrc[4] = {
        Ah + (size_t)bm * K, Al + (size_t)bm * K,
        Bh + (size_t)bn * K, Bl + (size_t)bn * K };

    // Per-lane ldmatrix row/chunk mapping.
    // A x4: matrices [m0-7|kLo],[m8-15|kLo],[m0-7|kHi],[m8-15|kHi]
    int rowA[2];
    rowA[0] = wm * 32 + (lane & 15);
    rowA[1] = rowA[0] + 16;
    const int caBit = lane >> 4;              // k-chunk bit for A
    // B x4: matrices [n0-7|kLo],[n0-7|kHi],[n8-15|kLo],[n8-15|kHi]
    int rowB[4];
#pragma unroll
    for (int bi = 0; bi < 4; ++bi)
        rowB[bi] = wn * 64 + bi * 16 + (lane & 7) + ((lane >> 4) << 3);
    const int cbBit = (lane >> 3) & 1;        // k-chunk bit for B

    float acc[2][8][4];
#pragma unroll
    for (int mi = 0; mi < 2; ++mi)
#pragma unroll
        for (int ni = 0; ni < 8; ++ni)
#pragma unroll
            for (int j = 0; j < 4; ++j) acc[mi][ni][j] = 0.f;

    auto load_stage = [&](int st, int kc) {
        uint32_t sb = sbase + st * STAGE_B;
#pragma unroll
        for (int t = 0; t < 4; ++t) {
            uint32_t tb = sb + t * TILE_B;
            const char* g = (const char*)(gsrc[t] + kc);
#pragma unroll
            for (int v = 0; v < 2; ++v) {
                int idx = tid + 256 * v;      // 0..511
                int r = idx >> 2;             // row 0..127
                int ch = idx & 3;             // 16B chunk
                CP_ASYNC16(tb + swz(r, ch), g + (size_t)r * K * 2 + ch * 16);
            }
        }
    };

    auto compute_stage = [&](int st) {
        uint32_t sb = sbase + st * STAGE_B;
#pragma unroll
        for (int ks = 0; ks < 2; ++ks) {      // two k16 steps per chunk
            uint32_t bhf[16], blf[16];
#pragma unroll
            for (int bi = 0; bi < 4; ++bi) {
                uint32_t off = swz(rowB[bi], 2 * ks + cbBit);
                ldsm_x4(&bhf[4 * bi], sb + 2 * TILE_B + off);
                ldsm_x4(&blf[4 * bi], sb + 3 * TILE_B + off);
            }
#pragma unroll
            for (int mi = 0; mi < 2; ++mi) {
                uint32_t ahf[4], alf[4];
                uint32_t off = swz(rowA[mi], 2 * ks + caBit);
                ldsm_x4(ahf, sb + off);
                ldsm_x4(alf, sb + TILE_B + off);
#pragma unroll
                for (int ni = 0; ni < 8; ++ni) {
                    // 3-term compensated: hi*hi + hi*lo + lo*hi
                    mma_bf16(acc[mi][ni], ahf, &bhf[2 * ni]);
                    mma_bf16(acc[mi][ni], ahf, &blf[2 * ni]);
                    mma_bf16(acc[mi][ni], alf, &bhf[2 * ni]);
                }
            }
        }
    };

    // Pipeline
#pragma unroll
    for (int s = 0; s < NSTAGE - 1; ++s) {
        load_stage(s, s * GKC);
        CP_COMMIT();
    }
    for (int c = 0; c < nchunk; ++c) {
        CP_WAIT(NSTAGE - 2);
        __syncthreads();
        compute_stage(c & (NSTAGE - 1));
        __syncthreads();
        int nx = c + NSTAGE - 1;
        if (nx < nchunk) {
            load_stage(nx & (NSTAGE - 1), nx * GKC);
            CP_COMMIT();
        }
    }

    // Epilogue: direct fp32 stores
    const int g = lane >> 2;
    const int t2 = (lane & 3) * 2;
#pragma unroll
    for (int mi = 0; mi < 2; ++mi)
#pragma unroll
        for (int ni = 0; ni < 8; ++ni) {
            int row = bm + wm * 32 + mi * 16 + g;
            int col = bn + wn * 64 + ni * 8 + t2;
            *(float2*)(C + (size_t)row * N + col) =
                make_float2(acc[mi][ni][0], acc[mi][ni][1]);
            *(float2*)(C + (size_t)(row + 8) * N + col) =
                make_float2(acc[mi][ni][2], acc[mi][ni][3]);
        }
}

// ---------------------------------------------------------------------------
// fp32 causal flash attention (unchanged — passing since R5)
// ---------------------------------------------------------------------------
#define AM 64
#define AN 64
#define QPAD 129
#define PPAD 65
#define ATTN_SMEM ((2 * AM * QPAD + AM * PPAD) * 4)

__global__ __launch_bounds__(256) void attn_kernel(
    const float* __restrict__ qkv, float* __restrict__ ctx)
{
    extern __shared__ float smf[];
    float* Qs  = smf;
    float* KVs = Qs + AM * QPAD;
    float* Ps  = KVs + AM * QPAD;

    const int tid = threadIdx.x;
    const int tx = tid & 15;
    const int ty = tid >> 4;
    const int qt = (gridDim.x - 1) - blockIdx.x;
    const int bh = blockIdx.y;
    const int b = bh >> 4;
    const int h = bh & 15;
    const int q0 = qt * AM;

    const size_t ld = QKV_N;
    const float* qbase = qkv + (size_t)b * SEQ * ld + (size_t)h * HDIM;
    const float* kbase = qbase + EMB;
    const float* vbase = qbase + 2 * EMB;

    for (int it = tid; it < AM * 32; it += 256) {
        int r = it >> 5;
        int c4 = (it & 31) << 2;
        float4 v = *(const float4*)(qbase + (size_t)(q0 + r) * ld + c4);
        float* d = &Qs[r * QPAD + c4];
        d[0] = v.x; d[1] = v.y; d[2] = v.z; d[3] = v.w;
    }

    float m_i[4], l_i[4], o[4][8];
#pragma unroll
    for (int i = 0; i < 4; i++) {
        m_i[i] = NEG_INF;
        l_i[i] = 0.f;
#pragma unroll
        for (int j = 0; j < 8; j++) o[i][j] = 0.f;
    }

    const float scale = 0.08838834764831845f;

    for (int kt = 0; kt <= qt; ++kt) {
        const int k0 = kt * AN;
        __syncthreads();

        for (int it = tid; it < AN * 32; it += 256) {
            int r = it >> 5;
            int c4 = (it & 31) << 2;
            float4 v = *(const float4*)(kbase + (size_t)(k0 + r) * ld + c4);
            float* d = &KVs[r * QPAD + c4];
            d[0] = v.x; d[1] = v.y; d[2] = v.z; d[3] = v.w;
        }
        __syncthreads();

        float s[4][4];
#pragma unroll
        for (int i = 0; i < 4; i++)
#pragma unroll
            for (int j = 0; j < 4; j++) s[i][j] = 0.f;

#pragma unroll 4
        for (int d = 0; d < HDIM; ++d) {
            float a_[4], b_[4];
#pragma unroll
            for (int i = 0; i < 4; i++) a_[i] = Qs[(ty + 16 * i) * QPAD + d];
#pragma unroll
            for (int j = 0; j < 4; j++) b_[j] = KVs[(tx + 16 * j) * QPAD + d];
#pragma unroll
            for (int i = 0; i < 4; i++)
#pragma unroll
                for (int j = 0; j < 4; j++)
                    s[i][j] += a_[i] * b_[j];
        }

        const bool diag = (kt == qt);
        float mt[4];
#pragma unroll
        for (int i = 0; i < 4; i++) {
            int qg = q0 + ty + 16 * i;
            float mx = NEG_INF;
#pragma unroll
            for (int j = 0; j < 4; j++) {
                float v = s[i][j] * scale;
                if (diag && (k0 + tx + 16 * j) > qg) v = NEG_INF;
                s[i][j] = v;
                mx = fmaxf(mx, v);
            }
#pragma unroll
            for (int off = 8; off > 0; off >>= 1)
                mx = fmaxf(mx, __shfl_xor_sync(0xffffffffu, mx, off));
            mt[i] = mx;
        }

#pragma unroll
        for (int i = 0; i < 4; i++) {
            float mnew = fmaxf(m_i[i], mt[i]);
            float alpha = __expf(m_i[i] - mnew);
            float lsum = 0.f;
#pragma unroll
            for (int j = 0; j < 4; j++) {
                float p = __expf(s[i][j] - mnew);
                s[i][j] = p;
                lsum += p;
            }
#pragma unroll
            for (int off = 8; off > 0; off >>= 1)
                lsum += __shfl_xor_sync(0xffffffffu, lsum, off);
            l_i[i] = l_i[i] * alpha + lsum;
            m_i[i] = mnew;
#pragma unroll
            for (int j = 0; j < 8; j++) o[i][j] *= alpha;
#pragma unroll
            for (int j = 0; j < 4; j++)
                Ps[(ty + 16 * i) * PPAD + tx + 16 * j] = s[i][j];
        }
        __syncthreads();

        for (int it = tid; it < AN * 32; it += 256) {
            int r = it >> 5;
            int c4 = (it & 31) << 2;
            float4 v = *(const float4*)(vbase + (size_t)(k0 + r) * ld + c4);
            float* d = &KVs[r * QPAD + c4];
            d[0] = v.x; d[1] = v.y; d[2] = v.z; d[3] = v.w;
        }
        __syncthreads();

#pragma unroll 8
        for (int k = 0; k < AN; ++k) {
            float pv[4], vv[8];
#pragma unroll
            for (int i = 0; i < 4; i++) pv[i] = Ps[(ty + 16 * i) * PPAD + k];
#pragma unroll
            for (int j = 0; j < 8; j++) vv[j] = KVs[k * QPAD + tx + 16 * j];
#pragma unroll
            for (int i = 0; i < 4; i++)
#pragma unroll
                for (int j = 0; j < 8; j++)
                    o[i][j] += pv[i] * vv[j];
        }
    }

#pragma unroll
    for (int i = 0; i < 4; i++) {
        float inv = 1.f / l_i[i];
        int r = q0 + ty + 16 * i;
        float* crow = ctx + (size_t)(b * SEQ + r) * EMB + h * HDIM;
#pragma unroll
        for (int j = 0; j < 8; j++)
            crow[tx + 16 * j] = o[i][j] * inv;
    }
}

// ---------------------------------------------------------------------------
// Launch
// ---------------------------------------------------------------------------
extern "C" void kernel_launch(void* const* d_in, const int* in_sizes, int n_in,
                              void* d_out, int out_size)
{
    const float* x     = (const float*)d_in[0];
    const float* w_qkv = (const float*)d_in[1];
    const float* w_out = (const float*)d_in[2];
    float* out = (float*)d_out;

    float *qkv = nullptr, *ctx = nullptr;
    __nv_bfloat16 *ah = nullptr, *al = nullptr;
    __nv_bfloat16 *wqh = nullptr, *wql = nullptr, *woh = nullptr, *wol = nullptr;
    cudaGetSymbolAddress((void**)&qkv, g_qkv);
    cudaGetSymbolAddress((void**)&ctx, g_ctx);
    cudaGetSymbolAddress((void**)&ah, g_ah);
    cudaGetSymbolAddress((void**)&al, g_al);
    cudaGetSymbolAddress((void**)&wqh, g_wqkv_h);
    cudaGetSymbolAddress((void**)&wql, g_wqkv_l);
    cudaGetSymbolAddress((void**)&woh, g_wout_h);
    cudaGetSymbolAddress((void**)&wol, g_wout_l);

    cudaFuncSetAttribute(gemm_tc_kernel,
                         cudaFuncAttributeMaxDynamicSharedMemorySize, GEMM_SMEM);
    cudaFuncSetAttribute(attn_kernel,
                         cudaFuncAttributeMaxDynamicSharedMemorySize, ATTN_SMEM);

    const int n4 = ROWS * EMB / 4;

    // 1) split x -> bf16 hi/lo; split+transpose w_qkv
    split_kernel<<<(n4 + 255) / 256, 256>>>(x, ah, al, n4);
    split_transpose_kernel<<<dim3(QKV_N / 32, EMB / 32), 256>>>(w_qkv, wqh, wql, EMB, QKV_N);

    // 2) QKV projection on tensor cores (HMMA): [4096,2048] @ [2048,6144]
    gemm_tc_kernel<<<dim3(QKV_N / GN, ROWS / GM), 256, GEMM_SMEM>>>(
        ah, al, wqh, wql, qkv, ROWS, QKV_N, EMB);

    // 3) Causal flash attention -> ctx
    attn_kernel<<<dim3(SEQ / AM, BATCH * HEADS), 256, ATTN_SMEM>>>(qkv, ctx);

    // 4) split ctx (reuse A buffers); split+transpose w_out
    split_kernel<<<(n4 + 255) / 256, 256>>>(ctx, ah, al, n4);
    split_transpose_kernel<<<dim3(EMB / 32, EMB / 32), 256>>>(w_out, woh, wol, EMB, EMB);

    // 5) Output projection on tensor cores: [4096,2048] @ [2048,2048]
    gemm_tc_kernel<<<dim3(EMB / GN, ROWS / GM), 256, GEMM_SMEM>>>(
        ah, al, woh, wol, out, ROWS, EMB, EMB);
}

// round 12
// speedup vs baseline: 2.8477x; 1.6496x over previous
#include <cuda_runtime.h>
#include <cuda_bf16.h>
#include <cstdint>

// Problem constants
#define BATCH 2
#define SEQ   2048
#define EMB   2048
#define HEADS 16
#define HDIM  128
#define ROWS  (BATCH * SEQ)          // 4096
#define QKV_N (3 * EMB)              // 6144
#define NEG_INF (-__int_as_float(0x7f800000))

// ---------------------------------------------------------------------------
// Scratch (device globals — no allocation allowed)
// ---------------------------------------------------------------------------
__device__ __nv_bfloat16 g_qkvh[(size_t)ROWS * QKV_N];   // qkv hi [4096,6144]
__device__ __nv_bfloat16 g_qkvl[(size_t)ROWS * QKV_N];   // qkv lo
__device__ __nv_bfloat16 g_ah[(size_t)ROWS * EMB];       // A hi (x, then ctx)
__device__ __nv_bfloat16 g_al[(size_t)ROWS * EMB];       // A lo
__device__ __nv_bfloat16 g_wqkv_h[(size_t)QKV_N * EMB];  // w_qkv^T hi [6144,2048]
__device__ __nv_bfloat16 g_wqkv_l[(size_t)QKV_N * EMB];
__device__ __nv_bfloat16 g_wout_h[(size_t)EMB * EMB];    // w_out^T hi [2048,2048]
__device__ __nv_bfloat16 g_wout_l[(size_t)EMB * EMB];

// ---------------------------------------------------------------------------
// Family-wide (sm_103-legal) helpers: ldmatrix + mma.sync + cp.async
// ---------------------------------------------------------------------------
__device__ __forceinline__ uint32_t smem_u32(const void* p) {
    uint32_t a;
    asm("{ .reg .u64 t; cvta.to.shared.u64 t, %1; cvt.u32.u64 %0, t; }"
        : "=r"(a) : "l"(p));
    return a;
}

#define CP_ASYNC16(dst, src) \
    asm volatile("cp.async.cg.shared.global [%0], [%1], 16;" \
        :: "r"(dst), "l"(src))
#define CP_COMMIT() asm volatile("cp.async.commit_group;" ::: "memory")
#define CP_WAIT(N)  asm volatile("cp.async.wait_group %0;" :: "n"(N) : "memory")

__device__ __forceinline__ void ldsm_x4(uint32_t* r, uint32_t addr) {
    asm volatile("ldmatrix.sync.aligned.m8n8.x4.shared.b16 {%0,%1,%2,%3}, [%4];"
        : "=r"(r[0]), "=r"(r[1]), "=r"(r[2]), "=r"(r[3]) : "r"(addr));
}
__device__ __forceinline__ void ldsm_x4t(uint32_t* r, uint32_t addr) {
    asm volatile("ldmatrix.sync.aligned.m8n8.x4.trans.shared.b16 {%0,%1,%2,%3}, [%4];"
        : "=r"(r[0]), "=r"(r[1]), "=r"(r[2]), "=r"(r[3]) : "r"(addr));
}

__device__ __forceinline__ void mma_bf16(float* d, const uint32_t* a,
                                         const uint32_t* b) {
    asm volatile(
        "mma.sync.aligned.m16n8k16.row.col.f32.bf16.bf16.f32 "
        "{%0,%1,%2,%3}, {%4,%5,%6,%7}, {%8,%9}, {%0,%1,%2,%3};"
        : "+f"(d[0]), "+f"(d[1]), "+f"(d[2]), "+f"(d[3])
        : "r"(a[0]), "r"(a[1]), "r"(a[2]), "r"(a[3]), "r"(b[0]), "r"(b[1]));
}

// pack two floats into bf16x2 (hi part) and residual bf16x2 (lo part)
__device__ __forceinline__ void split2(float a, float b, uint32_t& h, uint32_t& l) {
    __nv_bfloat162 h2 = __float22bfloat162_rn(make_float2(a, b));
    float2 hf = __bfloat1622float2(h2);
    __nv_bfloat162 l2 = __float22bfloat162_rn(make_float2(a - hf.x, b - hf.y));
    h = *(uint32_t*)&h2;
    l = *(uint32_t*)&l2;
}

// ---------------------------------------------------------------------------
// fp32 -> (hi, lo) bf16 split, elementwise (vectorized x4)
// ---------------------------------------------------------------------------
__global__ __launch_bounds__(256) void split_kernel(
    const float* __restrict__ X, __nv_bfloat16* __restrict__ Hi,
    __nv_bfloat16* __restrict__ Lo, int n4)
{
    int i = blockIdx.x * 256 + threadIdx.x;
    if (i >= n4) return;
    float4 v = ((const float4*)X)[i];
    uint32_t h0, l0, h1, l1;
    split2(v.x, v.y, h0, l0);
    split2(v.z, v.w, h1, l1);
    uint32_t* Hp = (uint32_t*)(Hi + 4 * (size_t)i);
    uint32_t* Lp = (uint32_t*)(Lo + 4 * (size_t)i);
    Hp[0] = h0; Hp[1] = h1;
    Lp[0] = l0; Lp[1] = l1;
}

// ---------------------------------------------------------------------------
// fp32 W[K][N] -> bf16 hi/lo W^T[N][K] (tiled transpose)
// ---------------------------------------------------------------------------
__global__ __launch_bounds__(256) void split_transpose_kernel(
    const float* __restrict__ W, __nv_bfloat16* __restrict__ Th,
    __nv_bfloat16* __restrict__ Tl, int K, int N)
{
    __shared__ float t[32][33];
    const int n0 = blockIdx.x * 32;
    const int k0 = blockIdx.y * 32;
    const int tx = threadIdx.x & 31;
    const int ty = threadIdx.x >> 5;   // 0..7
#pragma unroll
    for (int i = 0; i < 4; ++i)
        t[ty + 8 * i][tx] = W[(size_t)(k0 + ty + 8 * i) * N + n0 + tx];
    __syncthreads();
#pragma unroll
    for (int i = 0; i < 4; ++i) {
        float v = t[tx][ty + 8 * i];
        __nv_bfloat16 h = __float2bfloat16(v);
        __nv_bfloat16 l = __float2bfloat16(v - __bfloat162float(h));
        size_t o = (size_t)(n0 + ty + 8 * i) * K + k0 + tx;
        Th[o] = h;
        Tl[o] = l;
    }
}

// ---------------------------------------------------------------------------
// bf16 hi/lo 3-term GEMM via mma.sync (HMMA), epilogue fp32 OR bf16 hi/lo
// ---------------------------------------------------------------------------
#define GM 128
#define GN 128
#define GKC 32
#define TILE_B 8192
#define STAGE_B (4 * TILE_B)
#define NSTAGE 4
#define GEMM_SMEM (NSTAGE * STAGE_B)  // 131072

__device__ __forceinline__ uint32_t swz(int row, int ch) {
    return (uint32_t)(row * 64 + ((ch ^ ((row >> 1) & 3)) << 4));
}

__global__ __launch_bounds__(256, 1) void gemm_tc_kernel(
    const __nv_bfloat16* __restrict__ Ah, const __nv_bfloat16* __restrict__ Al,
    const __nv_bfloat16* __restrict__ Bh, const __nv_bfloat16* __restrict__ Bl,
    float* __restrict__ C, __nv_bfloat16* __restrict__ Ch,
    __nv_bfloat16* __restrict__ Cl, int M, int N, int K)
{
    extern __shared__ char smc[];
    const uint32_t sbase = smem_u32(smc);
    const int tid = threadIdx.x;
    const int lane = tid & 31;
    const int wid = tid >> 5;
    const int wm = wid & 3;
    const int wn = wid >> 2;
    const int bn = blockIdx.x * GN;
    const int bm = blockIdx.y * GM;
    const int nchunk = K / GKC;

    const __nv_bfloat16* gsrc[4] = {
        Ah + (size_t)bm * K, Al + (size_t)bm * K,
        Bh + (size_t)bn * K, Bl + (size_t)bn * K };

    int rowA[2];
    rowA[0] = wm * 32 + (lane & 15);
    rowA[1] = rowA[0] + 16;
    const int caBit = lane >> 4;
    int rowB[4];
#pragma unroll
    for (int bi = 0; bi < 4; ++bi)
        rowB[bi] = wn * 64 + bi * 16 + (lane & 7) + ((lane >> 4) << 3);
    const int cbBit = (lane >> 3) & 1;

    float acc[2][8][4];
#pragma unroll
    for (int mi = 0; mi < 2; ++mi)
#pragma unroll
        for (int ni = 0; ni < 8; ++ni)
#pragma unroll
            for (int j = 0; j < 4; ++j) acc[mi][ni][j] = 0.f;

    auto load_stage = [&](int st, int kc) {
        uint32_t sb = sbase + st * STAGE_B;
#pragma unroll
        for (int t = 0; t < 4; ++t) {
            uint32_t tb = sb + t * TILE_B;
            const char* g = (const char*)(gsrc[t] + kc);
#pragma unroll
            for (int v = 0; v < 2; ++v) {
                int idx = tid + 256 * v;
                int r = idx >> 2;
                int ch = idx & 3;
                CP_ASYNC16(tb + swz(r, ch), g + (size_t)r * K * 2 + ch * 16);
            }
        }
    };

    auto compute_stage = [&](int st) {
        uint32_t sb = sbase + st * STAGE_B;
#pragma unroll
        for (int ks = 0; ks < 2; ++ks) {
            uint32_t bhf[16], blf[16];
#pragma unroll
            for (int bi = 0; bi < 4; ++bi) {
                uint32_t off = swz(rowB[bi], 2 * ks + cbBit);
                ldsm_x4(&bhf[4 * bi], sb + 2 * TILE_B + off);
                ldsm_x4(&blf[4 * bi], sb + 3 * TILE_B + off);
            }
#pragma unroll
            for (int mi = 0; mi < 2; ++mi) {
                uint32_t ahf[4], alf[4];
                uint32_t off = swz(rowA[mi], 2 * ks + caBit);
                ldsm_x4(ahf, sb + off);
                ldsm_x4(alf, sb + TILE_B + off);
#pragma unroll
                for (int ni = 0; ni < 8; ++ni) {
                    mma_bf16(acc[mi][ni], ahf, &bhf[2 * ni]);
                    mma_bf16(acc[mi][ni], ahf, &blf[2 * ni]);
                    mma_bf16(acc[mi][ni], alf, &bhf[2 * ni]);
                }
            }
        }
    };

#pragma unroll
    for (int s = 0; s < NSTAGE - 1; ++s) {
        load_stage(s, s * GKC);
        CP_COMMIT();
    }
    for (int c = 0; c < nchunk; ++c) {
        CP_WAIT(NSTAGE - 2);
        __syncthreads();
        compute_stage(c & (NSTAGE - 1));
        __syncthreads();
        int nx = c + NSTAGE - 1;
        if (nx < nchunk) {
            load_stage(nx & (NSTAGE - 1), nx * GKC);
            CP_COMMIT();
        }
    }

    const int g = lane >> 2;
    const int t2 = (lane & 3) * 2;
    if (Ch == nullptr) {
#pragma unroll
        for (int mi = 0; mi < 2; ++mi)
#pragma unroll
            for (int ni = 0; ni < 8; ++ni) {
                int row = bm + wm * 32 + mi * 16 + g;
                int col = bn + wn * 64 + ni * 8 + t2;
                *(float2*)(C + (size_t)row * N + col) =
                    make_float2(acc[mi][ni][0], acc[mi][ni][1]);
                *(float2*)(C + (size_t)(row + 8) * N + col) =
                    make_float2(acc[mi][ni][2], acc[mi][ni][3]);
            }
    } else {
#pragma unroll
        for (int mi = 0; mi < 2; ++mi)
#pragma unroll
            for (int ni = 0; ni < 8; ++ni) {
                int row = bm + wm * 32 + mi * 16 + g;
                int col = bn + wn * 64 + ni * 8 + t2;
                uint32_t h, l;
                split2(acc[mi][ni][0], acc[mi][ni][1], h, l);
                *(uint32_t*)(Ch + (size_t)row * N + col) = h;
                *(uint32_t*)(Cl + (size_t)row * N + col) = l;
                split2(acc[mi][ni][2], acc[mi][ni][3], h, l);
                *(uint32_t*)(Ch + (size_t)(row + 8) * N + col) = h;
                *(uint32_t*)(Cl + (size_t)(row + 8) * N + col) = l;
            }
    }
}

// ---------------------------------------------------------------------------
// HMMA causal flash attention (bf16 hi/lo 3-term, fp32 accum)
// BM=BN=64, 128 threads (4 warps, 16 q-rows each). Smem: Q/K/V hi+lo tiles,
// each [64 rows][128 bf16 = 256B] with XOR-swizzled 16B chunks. 96 KB total.
// K and V committed as separate cp.async groups: V load hidden behind S+softmax.
// ---------------------------------------------------------------------------
#define ATM 64
#define ATT_TILE 16384              // 64 * 256
#define SQH 0
#define SQL (1 * ATT_TILE)
#define SKH (2 * ATT_TILE)
#define SKL (3 * ATT_TILE)
#define SVH (4 * ATT_TILE)
#define SVL (5 * ATT_TILE)
#define ATT_SMEM (6 * ATT_TILE)     // 98304

__device__ __forceinline__ uint32_t aswz(int r, int ch) {
    return (uint32_t)(r * 256 + ((ch ^ (r & 7)) << 4));
}

__global__ __launch_bounds__(128) void attn_tc_kernel(
    const __nv_bfloat16* __restrict__ qkvh,
    const __nv_bfloat16* __restrict__ qkvl,
    __nv_bfloat16* __restrict__ ch, __nv_bfloat16* __restrict__ cl)
{
    extern __shared__ char sma[];
    const uint32_t sb = smem_u32(sma);
    const int tid = threadIdx.x;
    const int lane = tid & 31;
    const int wid = tid >> 5;
    const int wbase = wid * 16;           // warp's q-row base within tile
    const int g = lane >> 2;
    const int t2 = (lane & 3) * 2;
    const int qt = (gridDim.x - 1) - blockIdx.x;  // longest first
    const int bh = blockIdx.y;
    const int b = bh >> 4;
    const int h = bh & 15;
    const int q0 = qt * ATM;

    const size_t GROW = 2 * (size_t)QKV_N;    // gmem row stride, bytes
    const char* qkvh_c = (const char*)qkvh;
    const char* qkvl_c = (const char*)qkvl;
    // byte offsets of this head's Q/K/V columns within a qkv row
    // layout per row: Q[0..EMB) | K[EMB..2*EMB) | V[2*EMB..3*EMB), bf16 elems
    const size_t offQ = (size_t)h * HDIM * 2;                 // h*256
    const size_t offK = ((size_t)EMB + h * HDIM) * 2;         // 4096 + h*256
    const size_t offV = ((size_t)2 * EMB + h * HDIM) * 2;     // 8192 + h*256

    auto load_tile = [&](uint32_t sdst, const char* gsrc) {
#pragma unroll
        for (int v = 0; v < 8; ++v) {
            int idx = tid + 128 * v;
            int r = idx >> 4;
            int c = idx & 15;
            CP_ASYNC16(sdst + aswz(r, c), gsrc + (size_t)r * GROW + c * 16);
        }
    };

    // Q tiles (hi/lo)
    {
        const size_t gq = (size_t)(b * SEQ + q0) * GROW + offQ;
        load_tile(sb + SQH, qkvh_c + gq);
        load_tile(sb + SQL, qkvl_c + gq);
        CP_COMMIT();
    }

    float o[16][4];
#pragma unroll
    for (int ni = 0; ni < 16; ++ni)
#pragma unroll
        for (int j = 0; j < 4; ++j) o[ni][j] = 0.f;
    float m0 = NEG_INF, m1 = NEG_INF, l0 = 0.f, l1 = 0.f;
    const float scale = 0.08838834764831845f;  // 1/sqrt(128)

    // ldmatrix lane address components
    const int rA = wbase + (lane & 15);               // Q rows (A operand)
    const int cAbit = lane >> 4;
    const int rB = (lane & 7) + ((lane >> 4) << 3);   // K rows base (B operand)
    const int cBbit = (lane >> 3) & 1;
    const int rVb = (lane & 7) + (((lane >> 3) & 1) << 3);  // V rows base
    const int cVbit = (lane >> 4) & 1;

    for (int kt = 0; kt <= qt; ++kt) {
        const int k0 = kt * ATM;
        {
            const size_t gr = (size_t)(b * SEQ + k0) * GROW;
            load_tile(sb + SKH, qkvh_c + gr + offK);
            load_tile(sb + SKL, qkvl_c + gr + offK);
            CP_COMMIT();                       // group: K
            load_tile(sb + SVH, qkvh_c + gr + offV);
            load_tile(sb + SVL, qkvl_c + gr + offV);
            CP_COMMIT();                       // group: V
        }
        CP_WAIT(1);        // K (and Q) ready; V may still be in flight
        __syncthreads();

        // ---- S = Q @ K^T (warp: 16 x 64), 3-term compensated ----
        float s[8][4];
#pragma unroll
        for (int ni = 0; ni < 8; ++ni)
#pragma unroll
            for (int j = 0; j < 4; ++j) s[ni][j] = 0.f;

#pragma unroll
        for (int ks = 0; ks < 8; ++ks) {
            uint32_t qh4[4], ql4[4];
            uint32_t offA = aswz(rA, 2 * ks + cAbit);
            ldsm_x4(qh4, sb + SQH + offA);
            ldsm_x4(ql4, sb + SQL + offA);
            uint32_t kh[16], klo[16];
#pragma unroll
            for (int bi = 0; bi < 4; ++bi) {
                uint32_t offB = aswz(bi * 16 + rB, 2 * ks + cBbit);
                ldsm_x4(&kh[4 * bi], sb + SKH + offB);
                ldsm_x4(&klo[4 * bi], sb + SKL + offB);
            }
#pragma unroll
            for (int ni = 0; ni < 8; ++ni) {
                mma_bf16(s[ni], qh4, &kh[2 * ni]);
                mma_bf16(s[ni], qh4, &klo[2 * ni]);
                mma_bf16(s[ni], ql4, &kh[2 * ni]);
            }
        }

        // ---- scale + causal mask + online softmax ----
        const bool diag = (kt == qt);
        const int grow0 = q0 + wbase + g;       // rows g, g+8
        float mt0 = NEG_INF, mt1 = NEG_INF;
#pragma unroll
        for (int ni = 0; ni < 8; ++ni) {
            int gcol = k0 + ni * 8 + t2;
#pragma unroll
            for (int e = 0; e < 4; ++e) {
                float v = s[ni][e] * scale;
                if (diag) {
                    int r = grow0 + ((e >> 1) << 3);
                    int cc = gcol + (e & 1);
                    if (cc > r) v = NEG_INF;
                }
                s[ni][e] = v;
            }
            mt0 = fmaxf(mt0, fmaxf(s[ni][0], s[ni][1]));
            mt1 = fmaxf(mt1, fmaxf(s[ni][2], s[ni][3]));
        }
#pragma unroll
        for (int off = 1; off <= 2; off <<= 1) {
            mt0 = fmaxf(mt0, __shfl_xor_sync(0xffffffffu, mt0, off));
            mt1 = fmaxf(mt1, __shfl_xor_sync(0xffffffffu, mt1, off));
        }
        float mn0 = fmaxf(m0, mt0), mn1 = fmaxf(m1, mt1);
        float a0 = __expf(m0 - mn0), a1 = __expf(m1 - mn1);
        float sum0 = 0.f, sum1 = 0.f;
#pragma unroll
        for (int ni = 0; ni < 8; ++ni) {
            s[ni][0] = __expf(s[ni][0] - mn0);
            s[ni][1] = __expf(s[ni][1] - mn0);
            s[ni][2] = __expf(s[ni][2] - mn1);
            s[ni][3] = __expf(s[ni][3] - mn1);
            sum0 += s[ni][0] + s[ni][1];
            sum1 += s[ni][2] + s[ni][3];
        }
#pragma unroll
        for (int off = 1; off <= 2; off <<= 1) {
            sum0 += __shfl_xor_sync(0xffffffffu, sum0, off);
            sum1 += __shfl_xor_sync(0xffffffffu, sum1, off);
        }
        l0 = l0 * a0 + sum0;
        l1 = l1 * a1 + sum1;
        m0 = mn0; m1 = mn1;
#pragma unroll
        for (int ni = 0; ni < 16; ++ni) {
            o[ni][0] *= a0; o[ni][1] *= a0;
            o[ni][2] *= a1; o[ni][3] *= a1;
        }

        // ---- pack P to bf16 hi/lo A-fragments ----
        uint32_t ph[4][4], pl[4][4];
#pragma unroll
        for (int k2 = 0; k2 < 4; ++k2) {
#pragma unroll
            for (int hf = 0; hf < 2; ++hf) {
                int tI = 2 * k2 + hf;
                split2(s[tI][0], s[tI][1], ph[k2][2 * hf], pl[k2][2 * hf]);
                split2(s[tI][2], s[tI][3], ph[k2][2 * hf + 1], pl[k2][2 * hf + 1]);
            }
        }

        CP_WAIT(0);        // V ready
        __syncthreads();

        // ---- O += P @ V (warp: 16 x 128), 3-term compensated ----
#pragma unroll
        for (int k2 = 0; k2 < 4; ++k2) {
#pragma unroll
            for (int dv = 0; dv < 8; ++dv) {
                uint32_t vh4[4], vl4[4];
                uint32_t offV2 = aswz(k2 * 16 + rVb, 2 * dv + cVbit);
                ldsm_x4t(vh4, sb + SVH + offV2);
                ldsm_x4t(vl4, sb + SVL + offV2);
                mma_bf16(o[2 * dv], ph[k2], &vh4[0]);
                mma_bf16(o[2 * dv], ph[k2], &vl4[0]);
                mma_bf16(o[2 * dv], pl[k2], &vh4[0]);
                mma_bf16(o[2 * dv + 1], ph[k2], &vh4[2]);
                mma_bf16(o[2 * dv + 1], ph[k2], &vl4[2]);
                mma_bf16(o[2 * dv + 1], pl[k2], &vh4[2]);
            }
        }
        __syncthreads();   // all warps done with K/V smem before next load
    }

    // ---- epilogue: normalize, write ctx as bf16 hi/lo ----
    const float inv0 = 1.f / l0;
    const float inv1 = 1.f / l1;
    const int grow = b * SEQ + q0 + wbase + g;
    const int gcol = h * HDIM + t2;
#pragma unroll
    for (int ni = 0; ni < 16; ++ni) {
        uint32_t hh, ll;
        int col = gcol + ni * 8;
        split2(o[ni][0] * inv0, o[ni][1] * inv0, hh, ll);
        *(uint32_t*)(ch + (size_t)grow * EMB + col) = hh;
        *(uint32_t*)(cl + (size_t)grow * EMB + col) = ll;
        split2(o[ni][2] * inv1, o[ni][3] * inv1, hh, ll);
        *(uint32_t*)(ch + (size_t)(grow + 8) * EMB + col) = hh;
        *(uint32_t*)(cl + (size_t)(grow + 8) * EMB + col) = ll;
    }
}

// ---------------------------------------------------------------------------
// Launch
// ---------------------------------------------------------------------------
extern "C" void kernel_launch(void* const* d_in, const int* in_sizes, int n_in,
                              void* d_out, int out_size)
{
    const float* x     = (const float*)d_in[0];
    const float* w_qkv = (const float*)d_in[1];
    const float* w_out = (const float*)d_in[2];
    float* out = (float*)d_out;

    __nv_bfloat16 *qkvh = nullptr, *qkvl = nullptr, *ah = nullptr, *al = nullptr;
    __nv_bfloat16 *wqh = nullptr, *wql = nullptr, *woh = nullptr, *wol = nullptr;
    cudaGetSymbolAddress((void**)&qkvh, g_qkvh);
    cudaGetSymbolAddress((void**)&qkvl, g_qkvl);
    cudaGetSymbolAddress((void**)&ah, g_ah);
    cudaGetSymbolAddress((void**)&al, g_al);
    cudaGetSymbolAddress((void**)&wqh, g_wqkv_h);
    cudaGetSymbolAddress((void**)&wql, g_wqkv_l);
    cudaGetSymbolAddress((void**)&woh, g_wout_h);
    cudaGetSymbolAddress((void**)&wol, g_wout_l);

    cudaFuncSetAttribute(gemm_tc_kernel,
                         cudaFuncAttributeMaxDynamicSharedMemorySize, GEMM_SMEM);
    cudaFuncSetAttribute(attn_tc_kernel,
                         cudaFuncAttributeMaxDynamicSharedMemorySize, ATT_SMEM);

    const int n4 = ROWS * EMB / 4;

    // 1) split x -> bf16 hi/lo; split+transpose both weights
    split_kernel<<<(n4 + 255) / 256, 256>>>(x, ah, al, n4);
    split_transpose_kernel<<<dim3(QKV_N / 32, EMB / 32), 256>>>(w_qkv, wqh, wql, EMB, QKV_N);
    split_transpose_kernel<<<dim3(EMB / 32, EMB / 32), 256>>>(w_out, woh, wol, EMB, EMB);

    // 2) QKV projection (HMMA), writes qkv as bf16 hi/lo directly
    gemm_tc_kernel<<<dim3(QKV_N / GN, ROWS / GM), 256, GEMM_SMEM>>>(
        ah, al, wqh, wql, nullptr, qkvh, qkvl, ROWS, QKV_N, EMB);

    // 3) Causal flash attention (HMMA), writes ctx as bf16 hi/lo (into ah/al)
    attn_tc_kernel<<<dim3(SEQ / ATM, BATCH * HEADS), 128, ATT_SMEM>>>(
        qkvh, qkvl, ah, al);

    // 4) Output projection (HMMA), fp32 result
    gemm_tc_kernel<<<dim3(EMB / GN, ROWS / GM), 256, GEMM_SMEM>>>(
        ah, al, woh, wol, out, nullptr, nullptr, ROWS, EMB, EMB);
}

// round 13
// speedup vs baseline: 3.2383x; 1.1372x over previous
#include <cuda_runtime.h>
#include <cuda_bf16.h>
#include <cstdint>

// Problem constants
#define BATCH 2
#define SEQ   2048
#define EMB   2048
#define HEADS 16
#define HDIM  128
#define ROWS  (BATCH * SEQ)          // 4096
#define QKV_N (3 * EMB)              // 6144
#define NEG_INF (-__int_as_float(0x7f800000))

// ---------------------------------------------------------------------------
// Scratch (device globals — no allocation allowed)
// ---------------------------------------------------------------------------
__device__ __nv_bfloat16 g_qkvh[(size_t)ROWS * QKV_N];   // qkv hi [4096,6144]
__device__ __nv_bfloat16 g_qkvl[(size_t)ROWS * QKV_N];   // qkv lo
__device__ __nv_bfloat16 g_ah[(size_t)ROWS * EMB];       // A hi (x, then ctx)
__device__ __nv_bfloat16 g_al[(size_t)ROWS * EMB];       // A lo
__device__ __nv_bfloat16 g_wqkv_h[(size_t)QKV_N * EMB];  // w_qkv^T hi [6144,2048]
__device__ __nv_bfloat16 g_wqkv_l[(size_t)QKV_N * EMB];
__device__ __nv_bfloat16 g_wout_h[(size_t)EMB * EMB];    // w_out^T hi [2048,2048]
__device__ __nv_bfloat16 g_wout_l[(size_t)EMB * EMB];

// ---------------------------------------------------------------------------
// Family-wide (sm_103-legal) helpers: ldmatrix + mma.sync + cp.async
// ---------------------------------------------------------------------------
__device__ __forceinline__ uint32_t smem_u32(const void* p) {
    uint32_t a;
    asm("{ .reg .u64 t; cvta.to.shared.u64 t, %1; cvt.u32.u64 %0, t; }"
        : "=r"(a) : "l"(p));
    return a;
}

#define CP_ASYNC16(dst, src) \
    asm volatile("cp.async.cg.shared.global [%0], [%1], 16;" \
        :: "r"(dst), "l"(src))
#define CP_COMMIT() asm volatile("cp.async.commit_group;" ::: "memory")
#define CP_WAIT(N)  asm volatile("cp.async.wait_group %0;" :: "n"(N) : "memory")

__device__ __forceinline__ void ldsm_x4(uint32_t* r, uint32_t addr) {
    asm volatile("ldmatrix.sync.aligned.m8n8.x4.shared.b16 {%0,%1,%2,%3}, [%4];"
        : "=r"(r[0]), "=r"(r[1]), "=r"(r[2]), "=r"(r[3]) : "r"(addr));
}
__device__ __forceinline__ void ldsm_x4t(uint32_t* r, uint32_t addr) {
    asm volatile("ldmatrix.sync.aligned.m8n8.x4.trans.shared.b16 {%0,%1,%2,%3}, [%4];"
        : "=r"(r[0]), "=r"(r[1]), "=r"(r[2]), "=r"(r[3]) : "r"(addr));
}

__device__ __forceinline__ void mma_bf16(float* d, const uint32_t* a,
                                         const uint32_t* b) {
    asm volatile(
        "mma.sync.aligned.m16n8k16.row.col.f32.bf16.bf16.f32 "
        "{%0,%1,%2,%3}, {%4,%5,%6,%7}, {%8,%9}, {%0,%1,%2,%3};"
        : "+f"(d[0]), "+f"(d[1]), "+f"(d[2]), "+f"(d[3])
        : "r"(a[0]), "r"(a[1]), "r"(a[2]), "r"(a[3]), "r"(b[0]), "r"(b[1]));
}

// pack two floats into bf16x2 (hi part) and residual bf16x2 (lo part)
__device__ __forceinline__ void split2(float a, float b, uint32_t& h, uint32_t& l) {
    __nv_bfloat162 h2 = __float22bfloat162_rn(make_float2(a, b));
    float2 hf = __bfloat1622float2(h2);
    __nv_bfloat162 l2 = __float22bfloat162_rn(make_float2(a - hf.x, b - hf.y));
    h = *(uint32_t*)&h2;
    l = *(uint32_t*)&l2;
}

// ---------------------------------------------------------------------------
// fp32 -> (hi, lo) bf16 split, elementwise (vectorized x4)
// ---------------------------------------------------------------------------
__global__ __launch_bounds__(256) void split_kernel(
    const float* __restrict__ X, __nv_bfloat16* __restrict__ Hi,
    __nv_bfloat16* __restrict__ Lo, int n4)
{
    int i = blockIdx.x * 256 + threadIdx.x;
    if (i >= n4) return;
    float4 v = ((const float4*)X)[i];
    uint32_t h0, l0, h1, l1;
    split2(v.x, v.y, h0, l0);
    split2(v.z, v.w, h1, l1);
    uint32_t* Hp = (uint32_t*)(Hi + 4 * (size_t)i);
    uint32_t* Lp = (uint32_t*)(Lo + 4 * (size_t)i);
    Hp[0] = h0; Hp[1] = h1;
    Lp[0] = l0; Lp[1] = l1;
}

// ---------------------------------------------------------------------------
// fp32 W[K][N] -> bf16 hi/lo W^T[N][K] (tiled transpose)
// ---------------------------------------------------------------------------
__global__ __launch_bounds__(256) void split_transpose_kernel(
    const float* __restrict__ W, __nv_bfloat16* __restrict__ Th,
    __nv_bfloat16* __restrict__ Tl, int K, int N)
{
    __shared__ float t[32][33];
    const int n0 = blockIdx.x * 32;
    const int k0 = blockIdx.y * 32;
    const int tx = threadIdx.x & 31;
    const int ty = threadIdx.x >> 5;   // 0..7
#pragma unroll
    for (int i = 0; i < 4; ++i)
        t[ty + 8 * i][tx] = W[(size_t)(k0 + ty + 8 * i) * N + n0 + tx];
    __syncthreads();
#pragma unroll
    for (int i = 0; i < 4; ++i) {
        float v = t[tx][ty + 8 * i];
        __nv_bfloat16 h = __float2bfloat16(v);
        __nv_bfloat16 l = __float2bfloat16(v - __bfloat162float(h));
        size_t o = (size_t)(n0 + ty + 8 * i) * K + k0 + tx;
        Th[o] = h;
        Tl[o] = l;
    }
}

// ---------------------------------------------------------------------------
// bf16 hi/lo 3-term GEMM via mma.sync (HMMA), epilogue fp32 OR bf16 hi/lo
// 3-stage cp.async pipeline (96 KB smem) + regs<=128 => 2 CTAs/SM
// ---------------------------------------------------------------------------
#define GM 128
#define GN 128
#define GKC 32
#define TILE_B 8192
#define STAGE_B (4 * TILE_B)
#define NSTAGE 3
#define GEMM_SMEM (NSTAGE * STAGE_B)  // 98304

__device__ __forceinline__ uint32_t swz(int row, int ch) {
    return (uint32_t)(row * 64 + ((ch ^ ((row >> 1) & 3)) << 4));
}

__global__ __launch_bounds__(256, 2) void gemm_tc_kernel(
    const __nv_bfloat16* __restrict__ Ah, const __nv_bfloat16* __restrict__ Al,
    const __nv_bfloat16* __restrict__ Bh, const __nv_bfloat16* __restrict__ Bl,
    float* __restrict__ C, __nv_bfloat16* __restrict__ Ch,
    __nv_bfloat16* __restrict__ Cl, int M, int N, int K)
{
    extern __shared__ char smc[];
    const uint32_t sbase = smem_u32(smc);
    const int tid = threadIdx.x;
    const int lane = tid & 31;
    const int wid = tid >> 5;
    const int wm = wid & 3;
    const int wn = wid >> 2;
    const int bn = blockIdx.x * GN;
    const int bm = blockIdx.y * GM;
    const int nchunk = K / GKC;

    const __nv_bfloat16* gsrc[4] = {
        Ah + (size_t)bm * K, Al + (size_t)bm * K,
        Bh + (size_t)bn * K, Bl + (size_t)bn * K };

    int rowA[2];
    rowA[0] = wm * 32 + (lane & 15);
    rowA[1] = rowA[0] + 16;
    const int caBit = lane >> 4;
    int rowB[4];
#pragma unroll
    for (int bi = 0; bi < 4; ++bi)
        rowB[bi] = wn * 64 + bi * 16 + (lane & 7) + ((lane >> 4) << 3);
    const int cbBit = (lane >> 3) & 1;

    float acc[2][8][4];
#pragma unroll
    for (int mi = 0; mi < 2; ++mi)
#pragma unroll
        for (int ni = 0; ni < 8; ++ni)
#pragma unroll
            for (int j = 0; j < 4; ++j) acc[mi][ni][j] = 0.f;

    auto load_stage = [&](int st, int kc) {
        uint32_t sb = sbase + st * STAGE_B;
#pragma unroll
        for (int t = 0; t < 4; ++t) {
            uint32_t tb = sb + t * TILE_B;
            const char* g = (const char*)(gsrc[t] + kc);
#pragma unroll
            for (int v = 0; v < 2; ++v) {
                int idx = tid + 256 * v;
                int r = idx >> 2;
                int ch = idx & 3;
                CP_ASYNC16(tb + swz(r, ch), g + (size_t)r * K * 2 + ch * 16);
            }
        }
    };

    auto compute_stage = [&](int st) {
        uint32_t sb = sbase + st * STAGE_B;
#pragma unroll
        for (int ks = 0; ks < 2; ++ks) {
            uint32_t bhf[16], blf[16];
#pragma unroll
            for (int bi = 0; bi < 4; ++bi) {
                uint32_t off = swz(rowB[bi], 2 * ks + cbBit);
                ldsm_x4(&bhf[4 * bi], sb + 2 * TILE_B + off);
                ldsm_x4(&blf[4 * bi], sb + 3 * TILE_B + off);
            }
#pragma unroll
            for (int mi = 0; mi < 2; ++mi) {
                uint32_t ahf[4], alf[4];
                uint32_t off = swz(rowA[mi], 2 * ks + caBit);
                ldsm_x4(ahf, sb + off);
                ldsm_x4(alf, sb + TILE_B + off);
#pragma unroll
                for (int ni = 0; ni < 8; ++ni) {
                    mma_bf16(acc[mi][ni], ahf, &bhf[2 * ni]);
                    mma_bf16(acc[mi][ni], ahf, &blf[2 * ni]);
                    mma_bf16(acc[mi][ni], alf, &bhf[2 * ni]);
                }
            }
        }
    };

#pragma unroll
    for (int s = 0; s < NSTAGE - 1; ++s) {
        load_stage(s, s * GKC);
        CP_COMMIT();
    }
    for (int c = 0; c < nchunk; ++c) {
        CP_WAIT(NSTAGE - 2);
        __syncthreads();
        compute_stage(c % NSTAGE);
        __syncthreads();
        int nx = c + NSTAGE - 1;
        if (nx < nchunk) {
            load_stage(nx % NSTAGE, nx * GKC);
            CP_COMMIT();
        }
    }

    const int g = lane >> 2;
    const int t2 = (lane & 3) * 2;
    if (Ch == nullptr) {
#pragma unroll
        for (int mi = 0; mi < 2; ++mi)
#pragma unroll
            for (int ni = 0; ni < 8; ++ni) {
                int row = bm + wm * 32 + mi * 16 + g;
                int col = bn + wn * 64 + ni * 8 + t2;
                *(float2*)(C + (size_t)row * N + col) =
                    make_float2(acc[mi][ni][0], acc[mi][ni][1]);
                *(float2*)(C + (size_t)(row + 8) * N + col) =
                    make_float2(acc[mi][ni][2], acc[mi][ni][3]);
            }
    } else {
#pragma unroll
        for (int mi = 0; mi < 2; ++mi)
#pragma unroll
            for (int ni = 0; ni < 8; ++ni) {
                int row = bm + wm * 32 + mi * 16 + g;
                int col = bn + wn * 64 + ni * 8 + t2;
                uint32_t h, l;
                split2(acc[mi][ni][0], acc[mi][ni][1], h, l);
                *(uint32_t*)(Ch + (size_t)row * N + col) = h;
                *(uint32_t*)(Cl + (size_t)row * N + col) = l;
                split2(acc[mi][ni][2], acc[mi][ni][3], h, l);
                *(uint32_t*)(Ch + (size_t)(row + 8) * N + col) = h;
                *(uint32_t*)(Cl + (size_t)(row + 8) * N + col) = l;
            }
    }
}

// ---------------------------------------------------------------------------
// HMMA causal flash attention (bf16 hi/lo 3-term, fp32 accum)
// BM=BN=64, 128 threads (4 warps, 16 q-rows each). Smem: Q/K/V hi+lo tiles,
// each [64 rows][128 bf16 = 256B] with XOR-swizzled 16B chunks. 96 KB total.
// K and V committed as separate cp.async groups: V load hidden behind S+softmax.
// ---------------------------------------------------------------------------
#define ATM 64
#define ATT_TILE 16384              // 64 * 256
#define SQH 0
#define SQL (1 * ATT_TILE)
#define SKH (2 * ATT_TILE)
#define SKL (3 * ATT_TILE)
#define SVH (4 * ATT_TILE)
#define SVL (5 * ATT_TILE)
#define ATT_SMEM (6 * ATT_TILE)     // 98304

__device__ __forceinline__ uint32_t aswz(int r, int ch) {
    return (uint32_t)(r * 256 + ((ch ^ (r & 7)) << 4));
}

__global__ __launch_bounds__(128) void attn_tc_kernel(
    const __nv_bfloat16* __restrict__ qkvh,
    const __nv_bfloat16* __restrict__ qkvl,
    __nv_bfloat16* __restrict__ ch, __nv_bfloat16* __restrict__ cl)
{
    extern __shared__ char sma[];
    const uint32_t sb = smem_u32(sma);
    const int tid = threadIdx.x;
    const int lane = tid & 31;
    const int wid = tid >> 5;
    const int wbase = wid * 16;           // warp's q-row base within tile
    const int g = lane >> 2;
    const int t2 = (lane & 3) * 2;
    const int qt = (gridDim.x - 1) - blockIdx.x;  // longest first
    const int bh = blockIdx.y;
    const int b = bh >> 4;
    const int h = bh & 15;
    const int q0 = qt * ATM;

    const size_t GROW = 2 * (size_t)QKV_N;    // gmem row stride, bytes
    const char* qkvh_c = (const char*)qkvh;
    const char* qkvl_c = (const char*)qkvl;
    // byte offsets of this head's Q/K/V columns within a qkv row
    const size_t offQ = (size_t)h * HDIM * 2;                 // h*256
    const size_t offK = ((size_t)EMB + h * HDIM) * 2;         // 4096 + h*256
    const size_t offV = ((size_t)2 * EMB + h * HDIM) * 2;     // 8192 + h*256

    auto load_tile = [&](uint32_t sdst, const char* gsrc) {
#pragma unroll
        for (int v = 0; v < 8; ++v) {
            int idx = tid + 128 * v;
            int r = idx >> 4;
            int c = idx & 15;
            CP_ASYNC16(sdst + aswz(r, c), gsrc + (size_t)r * GROW + c * 16);
        }
    };

    // Q tiles (hi/lo)
    {
        const size_t gq = (size_t)(b * SEQ + q0) * GROW + offQ;
        load_tile(sb + SQH, qkvh_c + gq);
        load_tile(sb + SQL, qkvl_c + gq);
        CP_COMMIT();
    }

    float o[16][4];
#pragma unroll
    for (int ni = 0; ni < 16; ++ni)
#pragma unroll
        for (int j = 0; j < 4; ++j) o[ni][j] = 0.f;
    float m0 = NEG_INF, m1 = NEG_INF, l0 = 0.f, l1 = 0.f;
    const float scale = 0.08838834764831845f;  // 1/sqrt(128)

    // ldmatrix lane address components
    const int rA = wbase + (lane & 15);               // Q rows (A operand)
    const int cAbit = lane >> 4;
    const int rB = (lane & 7) + ((lane >> 4) << 3);   // K rows base (B operand)
    const int cBbit = (lane >> 3) & 1;
    const int rVb = (lane & 7) + (((lane >> 3) & 1) << 3);  // V rows base
    const int cVbit = (lane >> 4) & 1;

    for (int kt = 0; kt <= qt; ++kt) {
        const int k0 = kt * ATM;
        {
            const size_t gr = (size_t)(b * SEQ + k0) * GROW;
            load_tile(sb + SKH, qkvh_c + gr + offK);
            load_tile(sb + SKL, qkvl_c + gr + offK);
            CP_COMMIT();                       // group: K
            load_tile(sb + SVH, qkvh_c + gr + offV);
            load_tile(sb + SVL, qkvl_c + gr + offV);
            CP_COMMIT();                       // group: V
        }
        CP_WAIT(1);        // K (and Q) ready; V may still be in flight
        __syncthreads();

        // ---- S = Q @ K^T (warp: 16 x 64), 3-term compensated ----
        float s[8][4];
#pragma unroll
        for (int ni = 0; ni < 8; ++ni)
#pragma unroll
            for (int j = 0; j < 4; ++j) s[ni][j] = 0.f;

#pragma unroll
        for (int ks = 0; ks < 8; ++ks) {
            uint32_t qh4[4], ql4[4];
            uint32_t offA = aswz(rA, 2 * ks + cAbit);
            ldsm_x4(qh4, sb + SQH + offA);
            ldsm_x4(ql4, sb + SQL + offA);
            uint32_t kh[16], klo[16];
#pragma unroll
            for (int bi = 0; bi < 4; ++bi) {
                uint32_t offB = aswz(bi * 16 + rB, 2 * ks + cBbit);
                ldsm_x4(&kh[4 * bi], sb + SKH + offB);
                ldsm_x4(&klo[4 * bi], sb + SKL + offB);
            }
#pragma unroll
            for (int ni = 0; ni < 8; ++ni) {
                mma_bf16(s[ni], qh4, &kh[2 * ni]);
                mma_bf16(s[ni], qh4, &klo[2 * ni]);
                mma_bf16(s[ni], ql4, &kh[2 * ni]);
            }
        }

        // ---- scale + causal mask + online softmax ----
        const bool diag = (kt == qt);
        const int grow0 = q0 + wbase + g;       // rows g, g+8
        float mt0 = NEG_INF, mt1 = NEG_INF;
#pragma unroll
        for (int ni = 0; ni < 8; ++ni) {
            int gcol = k0 + ni * 8 + t2;
#pragma unroll
            for (int e = 0; e < 4; ++e) {
                float v = s[ni][e] * scale;
                if (diag) {
                    int r = grow0 + ((e >> 1) << 3);
                    int cc = gcol + (e & 1);
                    if (cc > r) v = NEG_INF;
                }
                s[ni][e] = v;
            }
            mt0 = fmaxf(mt0, fmaxf(s[ni][0], s[ni][1]));
            mt1 = fmaxf(mt1, fmaxf(s[ni][2], s[ni][3]));
        }
#pragma unroll
        for (int off = 1; off <= 2; off <<= 1) {
            mt0 = fmaxf(mt0, __shfl_xor_sync(0xffffffffu, mt0, off));
            mt1 = fmaxf(mt1, __shfl_xor_sync(0xffffffffu, mt1, off));
        }
        float mn0 = fmaxf(m0, mt0), mn1 = fmaxf(m1, mt1);
        float a0 = __expf(m0 - mn0), a1 = __expf(m1 - mn1);
        float sum0 = 0.f, sum1 = 0.f;
#pragma unroll
        for (int ni = 0; ni < 8; ++ni) {
            s[ni][0] = __expf(s[ni][0] - mn0);
            s[ni][1] = __expf(s[ni][1] - mn0);
            s[ni][2] = __expf(s[ni][2] - mn1);
            s[ni][3] = __expf(s[ni][3] - mn1);
            sum0 += s[ni][0] + s[ni][1];
            sum1 += s[ni][2] + s[ni][3];
        }
#pragma unroll
        for (int off = 1; off <= 2; off <<= 1) {
            sum0 += __shfl_xor_sync(0xffffffffu, sum0, off);
            sum1 += __shfl_xor_sync(0xffffffffu, sum1, off);
        }
        l0 = l0 * a0 + sum0;
        l1 = l1 * a1 + sum1;
        m0 = mn0; m1 = mn1;
#pragma unroll
        for (int ni = 0; ni < 16; ++ni) {
            o[ni][0] *= a0; o[ni][1] *= a0;
            o[ni][2] *= a1; o[ni][3] *= a1;
        }

        // ---- pack P to bf16 hi/lo A-fragments ----
        uint32_t ph[4][4], pl[4][4];
#pragma unroll
        for (int k2 = 0; k2 < 4; ++k2) {
#pragma unroll
            for (int hf = 0; hf < 2; ++hf) {
                int tI = 2 * k2 + hf;
                split2(s[tI][0], s[tI][1], ph[k2][2 * hf], pl[k2][2 * hf]);
                split2(s[tI][2], s[tI][3], ph[k2][2 * hf + 1], pl[k2][2 * hf + 1]);
            }
        }

        CP_WAIT(0);        // V ready
        __syncthreads();

        // ---- O += P @ V (warp: 16 x 128), 3-term compensated ----
#pragma unroll
        for (int k2 = 0; k2 < 4; ++k2) {
#pragma unroll
            for (int dv = 0; dv < 8; ++dv) {
                uint32_t vh4[4], vl4[4];
                uint32_t offV2 = aswz(k2 * 16 + rVb, 2 * dv + cVbit);
                ldsm_x4t(vh4, sb + SVH + offV2);
                ldsm_x4t(vl4, sb + SVL + offV2);
                mma_bf16(o[2 * dv], ph[k2], &vh4[0]);
                mma_bf16(o[2 * dv], ph[k2], &vl4[0]);
                mma_bf16(o[2 * dv], pl[k2], &vh4[0]);
                mma_bf16(o[2 * dv + 1], ph[k2], &vh4[2]);
                mma_bf16(o[2 * dv + 1], ph[k2], &vl4[2]);
                mma_bf16(o[2 * dv + 1], pl[k2], &vh4[2]);
            }
        }
        __syncthreads();   // all warps done with K/V smem before next load
    }

    // ---- epilogue: normalize, write ctx as bf16 hi/lo ----
    const float inv0 = 1.f / l0;
    const float inv1 = 1.f / l1;
    const int grow = b * SEQ + q0 + wbase + g;
    const int gcol = h * HDIM + t2;
#pragma unroll
    for (int ni = 0; ni < 16; ++ni) {
        uint32_t hh, ll;
        int col = gcol + ni * 8;
        split2(o[ni][0] * inv0, o[ni][1] * inv0, hh, ll);
        *(uint32_t*)(ch + (size_t)grow * EMB + col) = hh;
        *(uint32_t*)(cl + (size_t)grow * EMB + col) = ll;
        split2(o[ni][2] * inv1, o[ni][3] * inv1, hh, ll);
        *(uint32_t*)(ch + (size_t)(grow + 8) * EMB + col) = hh;
        *(uint32_t*)(cl + (size_t)(grow + 8) * EMB + col) = ll;
    }
}

// ---------------------------------------------------------------------------
// Launch
// ---------------------------------------------------------------------------
extern "C" void kernel_launch(void* const* d_in, const int* in_sizes, int n_in,
                              void* d_out, int out_size)
{
    const float* x     = (const float*)d_in[0];
    const float* w_qkv = (const float*)d_in[1];
    const float* w_out = (const float*)d_in[2];
    float* out = (float*)d_out;

    __nv_bfloat16 *qkvh = nullptr, *qkvl = nullptr, *ah = nullptr, *al = nullptr;
    __nv_bfloat16 *wqh = nullptr, *wql = nullptr, *woh = nullptr, *wol = nullptr;
    cudaGetSymbolAddress((void**)&qkvh, g_qkvh);
    cudaGetSymbolAddress((void**)&qkvl, g_qkvl);
    cudaGetSymbolAddress((void**)&ah, g_ah);
    cudaGetSymbolAddress((void**)&al, g_al);
    cudaGetSymbolAddress((void**)&wqh, g_wqkv_h);
    cudaGetSymbolAddress((void**)&wql, g_wqkv_l);
    cudaGetSymbolAddress((void**)&woh, g_wout_h);
    cudaGetSymbolAddress((void**)&wol, g_wout_l);

    cudaFuncSetAttribute(gemm_tc_kernel,
                         cudaFuncAttributeMaxDynamicSharedMemorySize, GEMM_SMEM);
    cudaFuncSetAttribute(attn_tc_kernel,
                         cudaFuncAttributeMaxDynamicSharedMemorySize, ATT_SMEM);

    const int n4 = ROWS * EMB / 4;

    // 1) split x -> bf16 hi/lo; split+transpose both weights
    split_kernel<<<(n4 + 255) / 256, 256>>>(x, ah, al, n4);
    split_transpose_kernel<<<dim3(QKV_N / 32, EMB / 32), 256>>>(w_qkv, wqh, wql, EMB, QKV_N);
    split_transpose_kernel<<<dim3(EMB / 32, EMB / 32), 256>>>(w_out, woh, wol, EMB, EMB);

    // 2) QKV projection (HMMA), writes qkv as bf16 hi/lo directly
    gemm_tc_kernel<<<dim3(QKV_N / GN, ROWS / GM), 256, GEMM_SMEM>>>(
        ah, al, wqh, wql, nullptr, qkvh, qkvl, ROWS, QKV_N, EMB);

    // 3) Causal flash attention (HMMA), writes ctx as bf16 hi/lo (into ah/al)
    attn_tc_kernel<<<dim3(SEQ / ATM, BATCH * HEADS), 128, ATT_SMEM>>>(
        qkvh, qkvl, ah, al);

    // 4) Output projection (HMMA), fp32 result
    gemm_tc_kernel<<<dim3(EMB / GN, ROWS / GM), 256, GEMM_SMEM>>>(
        ah, al, woh, wol, out, nullptr, nullptr, ROWS, EMB, EMB);
}